// round 7
// baseline (speedup 1.0000x reference)
#include <cuda_runtime.h>
#include <cstdint>

#define NB   64
#define N    256
#define ND   511
#define BIGV 1e10f

// Diag-major: X[b][d][j] = cell (i=d-j, j).
__device__ float  g_Dd[NB * ND * N];
__device__ float4 g_W4[NB * ND * N];   // (wl, wd, wu, 0)
__device__ float  g_Ed[NB * ND * N];
__device__ float  g_Es[ND * N];

// ---- atomic-visibility smem mailbox ops (single vector volatile access) ----
__device__ __forceinline__ void st64(uint2* p, float z, unsigned tag) {
    unsigned a = (unsigned)__cvta_generic_to_shared(p);
    asm volatile("st.volatile.shared.v2.u32 [%0],{%1,%2};"
                 :: "r"(a), "r"(__float_as_uint(z)), "r"(tag) : "memory");
}
__device__ __forceinline__ uint2 ld64(const uint2* p) {
    unsigned a = (unsigned)__cvta_generic_to_shared((void*)p); uint2 v;
    asm volatile("ld.volatile.shared.v2.u32 {%0,%1},[%2];"
                 : "=r"(v.x), "=r"(v.y) : "r"(a) : "memory");
    return v;
}
__device__ __forceinline__ void st128(uint4* p, float e, float wl, float wd, unsigned tag) {
    unsigned a = (unsigned)__cvta_generic_to_shared(p);
    asm volatile("st.volatile.shared.v4.u32 [%0],{%1,%2,%3,%4};"
                 :: "r"(a), "r"(__float_as_uint(e)), "r"(__float_as_uint(wl)),
                    "r"(__float_as_uint(wd)), "r"(tag) : "memory");
}
__device__ __forceinline__ uint4 ld128(const uint4* p) {
    unsigned a = (unsigned)__cvta_generic_to_shared((void*)p); uint4 v;
    asm volatile("ld.volatile.shared.v4.u32 {%0,%1,%2,%3},[%4];"
                 : "=r"(v.x), "=r"(v.y), "=r"(v.z), "=r"(v.w) : "r"(a) : "memory");
    return v;
}

// Softmin cell — every float op bit-identical to the R4 passing kernel,
// INCLUDING the weights (w_k = expf(z_k - lse); this is rel_err-critical).
__device__ __forceinline__ void cell(float zl, float zd, float zu, float th,
                                     float& zc, float& wl, float& wd, float& wu) {
    const float zmax = fmaxf(fmaxf(zl, zd), zu);
    const float el = expf(__fsub_rn(zl, zmax));
    const float ed = expf(__fsub_rn(zd, zmax));
    const float eu = expf(__fsub_rn(zu, zmax));
    const float ssum = __fadd_rn(__fadd_rn(el, ed), eu);
    const float lse  = __fadd_rn(logf(ssum), zmax);
    const float R    = __fadd_rn(th, __fmul_rn(-0.01f, lse));
    zc = __fdiv_rn(-R, 0.01f);          // same op the R4 consumer applied to R
    wl = expf(__fsub_rn(zl, lse));
    wd = expf(__fsub_rn(zd, lse));
    wu = expf(__fsub_rn(zu, lse));
}

// ---------------------------------------------------------------------------
__global__ void shear_kernel(const float* __restrict__ D) {
    __shared__ float s[32][33];
    const int b = blockIdx.z, i0 = blockIdx.y * 32, j0 = blockIdx.x * 32;
    const int tx = threadIdx.x, ty = threadIdx.y;
    const float* Db = D + (size_t)b * N * N;
    #pragma unroll
    for (int r = ty; r < 32; r += 8) s[r][tx] = Db[(i0 + r) * N + j0 + tx];
    __syncthreads();
    float* out = g_Dd + (size_t)b * ND * N;
    for (int dd = ty; dd < 63; dd += 8) {
        int r = dd - tx;
        if (r >= 0 && r < 32) out[(i0 + j0 + dd) * N + (j0 + tx)] = s[r][tx];
    }
}

// ---------------------------------------------------------------------------
// Barrier-free DP: 4 warps/batch, 2 columns/thread (cA=64w+2*lane, cB=cA+1).
// j-1 -> j inside a warp via shfl; warp boundaries via tagged smem mailboxes.
// ---------------------------------------------------------------------------
__global__ __launch_bounds__(128) void dp_kernel() {
    __shared__ uint2 mbF[3][512];   // fwd boundary: z at diag e, tag=e+1
    __shared__ uint4 mbB[3][512];   // bwd boundary: (E(e), Wl(e), Wd(e+1)), tag=e+1

    const int b = blockIdx.x, tid = threadIdx.x;
    const int w = tid >> 5, lane = tid & 31;
    for (int k = tid; k < 3 * 512; k += 128) {
        ((uint2*)mbF)[k] = make_uint2(0u, 0u);
        ((uint4*)mbB)[k] = make_uint4(0u, 0u, 0u, 0u);
    }
    __syncthreads();

    const size_t base = (size_t)b * ND * N;
    const float* __restrict__ Dd = g_Dd + base;
    float4* __restrict__ W4 = g_W4 + base;
    float*  __restrict__ Ed = g_Ed + base;

    const int cA = w * 64 + 2 * lane, cB = cA + 1;
    const int d0 = w * 64, d1 = d0 + 318;
    const float ZBIG = __fdiv_rn(-BIGV, 0.01f);

    // ================= forward =================
    {
        float zA1 = ZBIG, zA2 = ZBIG, zB1 = ZBIG, zB2 = ZBIG;
        float mz1 = ZBIG, mz2 = ZBIG;
        float thA0 = Dd[(size_t)d0 * N + cA],     thB0 = Dd[(size_t)d0 * N + cB];
        float thA1 = Dd[(size_t)(d0+1) * N + cA], thB1 = Dd[(size_t)(d0+1) * N + cB];

        for (int d = d0; d <= d1; ++d) {
            const int iA = d - cA, iB = d - cB;
            const bool actA = (unsigned)iA < 256u, actB = (unsigned)iB < 256u;

            if (lane == 0 && w > 0 && actA) {            // boundary z(d-1, cA-1)
                uint2 m;
                do { m = ld64(&mbF[w - 1][d - 1]); } while (m.y != (unsigned)d);
                mz1 = __uint_as_float(m.x);
            }
            float zlA = __shfl_up_sync(0xffffffffu, zB1, 1);
            float zdA = __shfl_up_sync(0xffffffffu, zB2, 1);
            if (lane == 0) { zlA = (w > 0) ? mz1 : ZBIG; zdA = (w > 0) ? mz2 : ZBIG; }
            float zuA = zA1;
            if (iA == 0) { zuA = ZBIG; zdA = (cA == 0) ? __fdiv_rn(-0.0f, 0.01f) : ZBIG; }
            float zlB = zA1, zdB = zA2, zuB = zB1;
            if (iB == 0) { zuB = ZBIG; zdB = ZBIG; }

            float zcA, wlA, wdA, wuA, zcB, wlB, wdB, wuB;
            cell(zlA, zdA, zuA, thA0, zcA, wlA, wdA, wuA);
            cell(zlB, zdB, zuB, thB0, zcB, wlB, wdB, wuB);

            if (actA) W4[(size_t)d * N + cA] = make_float4(wlA, wdA, wuA, 0.f);
            if (actB) {
                W4[(size_t)d * N + cB] = make_float4(wlB, wdB, wuB, 0.f);
                if (lane == 31 && w < 3) st64(&mbF[w][d], zcB, (unsigned)(d + 1));
            }
            zA2 = zA1; zA1 = actA ? zcA : ZBIG;
            zB2 = zB1; zB1 = actB ? zcB : ZBIG;
            mz2 = mz1;
            thA0 = thA1; thB0 = thB1;
            if (d + 2 <= d1) {
                thA1 = Dd[(size_t)(d + 2) * N + cA];
                thB1 = Dd[(size_t)(d + 2) * N + cB];
            }
        }
    }

    // ================= backward =================
    {
        float eA1 = 0.f, eA2 = 0.f, eB1 = 0.f, eB2 = 0.f;
        float wlA1 = 0.f, wuA1 = 0.f, wdA1 = 0.f, wdA2 = 0.f;
        float wlB1 = 0.f, wuB1 = 0.f, wdB1 = 0.f, wdB2 = 0.f;
        float mbE2 = 0.f;
        float4 a0 = W4[(size_t)d1 * N + cA], b0 = W4[(size_t)d1 * N + cB];
        float4 a1 = W4[(size_t)(d1-1) * N + cA], b1 = W4[(size_t)(d1-1) * N + cB];

        for (int d = d1; d >= d0; --d) {
            const int iA = d - cA, iB = d - cB;
            const bool actA = (unsigned)iA < 256u, actB = (unsigned)iB < 256u;

            float sE1 = __shfl_down_sync(0xffffffffu, eA1, 1);
            float sE2 = __shfl_down_sync(0xffffffffu, eA2, 1);
            float sWl1 = __shfl_down_sync(0xffffffffu, wlA1, 1);
            float sWd2 = __shfl_down_sync(0xffffffffu, wdA2, 1);
            if (lane == 31 && w < 3 && actB) {           // boundary (E,Wl)(d+1), Wd(d+2)
                uint4 m;
                do { m = ld128(&mbB[w][d + 1]); } while (m.w != (unsigned)(d + 2));
                sE1 = __uint_as_float(m.x);
                sWl1 = __uint_as_float(m.y);
                sWd2 = __uint_as_float(m.z);
                sE2 = mbE2;
                mbE2 = sE1;
            }

            // cell A (col cA <= 254 always)
            const float t0A = __fmul_rn(wlB1, eB1);
            const float t1A = (iA < 255) ? __fmul_rn(wdB2, eB2) : 0.f;
            const float t2A = (iA < 255) ? __fmul_rn(wuA1, eA1) : 0.f;
            const float eA = __fadd_rn(__fadd_rn(t0A, t1A), t2A);

            // cell B
            const bool jltB = !(w == 3 && lane == 31);
            const float t0B = jltB ? __fmul_rn(sWl1, sE1) : 0.f;
            const float t1B = (jltB && iB < 255) ? __fmul_rn(sWd2, sE2) : 0.f;
            const float t2B = (iB < 255) ? __fmul_rn(wuB1, eB1) : 0.f;
            float eB = __fadd_rn(__fadd_rn(t0B, t1B), t2B);
            if (iB == 255 && cB == N - 1) eB = 1.0f;

            if (actA) {
                Ed[(size_t)d * N + cA] = eA;
                if (lane == 0 && w > 0)
                    st128(&mbB[w - 1][d], eA, a0.x, wdA1, (unsigned)(d + 1));
            }
            if (actB) Ed[(size_t)d * N + cB] = eB;

            eA2 = eA1; eA1 = actA ? eA : 0.f;
            eB2 = eB1; eB1 = actB ? eB : 0.f;
            wdA2 = wdA1; wdA1 = a0.y; wlA1 = a0.x; wuA1 = a0.z;
            wdB2 = wdB1; wdB1 = b0.y; wlB1 = b0.x; wuB1 = b0.z;
            a0 = a1; b0 = b1;
            if (d - 2 >= d0) {
                a1 = W4[(size_t)(d - 2) * N + cA];
                b1 = W4[(size_t)(d - 2) * N + cB];
            }
        }
    }
}

// ---------------------------------------------------------------------------
__global__ void reduce_kernel() {
    const int idx = blockIdx.x * blockDim.x + threadIdx.x;
    float s = 0.0f;
    #pragma unroll 4
    for (int b = 0; b < NB; ++b) s += g_Ed[(size_t)b * ND * N + idx];
    g_Es[idx] = s * (1.0f / NB);
}
__global__ void gather_kernel(float* __restrict__ out) {
    const int idx = blockIdx.x * blockDim.x + threadIdx.x;
    const int i = idx >> 8, j = idx & (N - 1);
    out[idx] = g_Es[(i + j) * N + j];
}

// ---------------------------------------------------------------------------
extern "C" void kernel_launch(void* const* d_in, const int* in_sizes, int n_in,
                              void* d_out, int out_size) {
    const float* D = (const float*)d_in[0];
    float* out = (float*)d_out;
    shear_kernel<<<dim3(8, 8, NB), dim3(32, 8)>>>(D);
    dp_kernel<<<NB, 128>>>();
    reduce_kernel<<<ND, 256>>>();
    gather_kernel<<<(N * N) / 256, 256>>>(out);
}

// round 8
// speedup vs baseline: 2.2265x; 2.2265x over previous
#include <cuda_runtime.h>

#define NB   64
#define N    256
#define ND   511          // number of anti-diagonals (2N-1)
#define BIGV 1e10f

// Scratch (device globals; no allocations allowed).
// Diag-major layout: X[b][d][j] = cell (i=d-j, j) of batch b.
__device__ float  g_Dd[NB * ND * N];   // sheared input costs
__device__ float4 g_W4[NB * ND * N];   // (wl, wd, wu, 0) per cell
__device__ float  g_Ed[NB * ND * N];   // per-batch E
__device__ float  g_Es[ND * N];        // batch-mean E (diag-major)

// ---------------------------------------------------------------------------
// Shear: row-major D -> diag-major g_Dd, coalesced both ways via smem tiles.
// ---------------------------------------------------------------------------
__global__ void shear_kernel(const float* __restrict__ D) {
    __shared__ float s[32][33];
    const int b  = blockIdx.z;
    const int i0 = blockIdx.y * 32;
    const int j0 = blockIdx.x * 32;
    const int tx = threadIdx.x, ty = threadIdx.y;

    const float* Db = D + (size_t)b * N * N;
    #pragma unroll
    for (int r = ty; r < 32; r += 8)
        s[r][tx] = Db[(i0 + r) * N + j0 + tx];
    __syncthreads();

    float* out = g_Dd + (size_t)b * ND * N;
    for (int dd = ty; dd < 63; dd += 8) {
        int r = dd - tx;
        if (r >= 0 && r < 32)
            out[(i0 + j0 + dd) * N + (j0 + tx)] = s[r][tx];
    }
}

// ---------------------------------------------------------------------------
// Fused forward + backward DP. One CTA per batch, thread j = column j.
// Every float op bit-identical to the R4 passing kernel (rel_err-critical):
// the smem now carries z = __fdiv_rn(-R, 0.01f) instead of R — the exact op
// every consumer applied to R in R4 — so consumer values are bit-identical
// while 2 of 3 divides per cell disappear.
// ---------------------------------------------------------------------------
__global__ __launch_bounds__(256) void dp_kernel() {
    __shared__ float sb[10][N];

    const int b = blockIdx.x;
    const size_t base = (size_t)b * ND * N;
    const float*  __restrict__ Dd = g_Dd + base;
    float4*       __restrict__ W4 = g_W4 + base;
    float*        __restrict__ Ed = g_Ed + base;

    const int j = threadIdx.x;
    const bool jgt0 = (j > 0);
    const bool jlt  = (j < N - 1);
    const float ZBIG = __fdiv_rn(-BIGV, 0.01f);

    // ---------------- forward ----------------
    {
        float *zcur = sb[0], *zp1 = sb[1], *zp2 = sb[2];
        // Dd prefetch ring, depth 4
        float th0 = Dd[j];
        float th1 = Dd[N + j];
        float th2 = Dd[2 * N + j];
        float th3 = Dd[3 * N + j];

        for (int d = 0; d < ND; ++d) {
            float thN = 0.0f;
            if (d + 4 < ND) thN = Dd[(size_t)(d + 4) * N + j];

            const int i = d - j;
            if ((unsigned)i < (unsigned)N) {
                const float zl = jgt0    ? zp1[j - 1] : ZBIG;       // z(i, j-1)
                const float zu = (i > 0) ? zp1[j]     : ZBIG;       // z(i-1, j)
                float zd;                                           // z(i-1, j-1)
                if (i > 0 && jgt0)       zd = zp2[j - 1];
                else                     zd = (i == 0 && j == 0)
                                              ? __fdiv_rn(-0.0f, 0.01f) : ZBIG;

                const float zmax = fmaxf(fmaxf(zl, zd), zu);
                const float el = expf(__fsub_rn(zl, zmax));
                const float ed = expf(__fsub_rn(zd, zmax));
                const float eu = expf(__fsub_rn(zu, zmax));
                const float ssum = __fadd_rn(__fadd_rn(el, ed), eu);
                const float lse  = __fadd_rn(logf(ssum), zmax);
                const float R    = __fadd_rn(th0, __fmul_rn(-0.01f, lse));

                W4[(size_t)d * N + j] = make_float4(expf(__fsub_rn(zl, lse)),
                                                   expf(__fsub_rn(zd, lse)),
                                                   expf(__fsub_rn(zu, lse)),
                                                   0.0f);
                zcur[j] = __fdiv_rn(-R, 0.01f);
            }
            __syncthreads();
            th0 = th1; th1 = th2; th2 = th3; th3 = thN;
            float* t = zp2; zp2 = zp1; zp1 = zcur; zcur = t;
        }
    }

    // ---------------- backward ----------------
    {
        float *ecur = sb[0], *ep1 = sb[1], *ep2 = sb[2];
        float *qlc  = sb[3], *qlp = sb[4];                  // w_left  (cur, d+1)
        float *quc  = sb[5], *qup = sb[6];                  // w_up    (cur, d+1)
        float *qdc  = sb[7], *qdp1 = sb[8], *qdp2 = sb[9];  // w_diag  (cur, d+1, d+2)

        // W4 prefetch ring, depth 4 (q0 = W at current diag)
        float4 q0 = W4[(size_t)(ND - 1) * N + j];
        float4 q1 = W4[(size_t)(ND - 2) * N + j];
        float4 q2 = W4[(size_t)(ND - 3) * N + j];
        float4 q3 = W4[(size_t)(ND - 4) * N + j];

        for (int d = ND - 1; d >= 0; --d) {
            float4 qN = make_float4(0.f, 0.f, 0.f, 0.f);
            if (d - 4 >= 0) qN = W4[(size_t)(d - 4) * N + j];

            const int i = d - j;
            if ((unsigned)i < (unsigned)N) {
                float e;
                if (i == N - 1 && j == N - 1) {
                    e = 1.0f;
                } else {
                    float t0 = 0.0f, t1 = 0.0f, t2 = 0.0f;
                    if (jlt)                       // from (i, j+1)  @ diag d+1
                        t0 = __fmul_rn(qlp[j + 1], ep1[j + 1]);
                    if (i < N - 1) {
                        if (jlt)                   // from (i+1,j+1) @ diag d+2
                            t1 = __fmul_rn(qdp2[j + 1], ep2[j + 1]);
                        t2 = __fmul_rn(qup[j], ep1[j]);   // from (i+1, j) @ d+1
                    }
                    e = __fadd_rn(__fadd_rn(t0, t1), t2);
                }
                Ed[(size_t)d * N + j] = e;
                ecur[j] = e;
                qlc[j] = q0.x;       // wl at diag d
                quc[j] = q0.z;       // wu at diag d
                qdc[j] = q0.y;       // wd at diag d
            }
            __syncthreads();
            q0 = q1; q1 = q2; q2 = q3; q3 = qN;
            float* t;
            t = ep2;  ep2  = ep1;  ep1 = ecur; ecur = t;
            t = qlp;  qlp  = qlc;  qlc = t;
            t = qup;  qup  = quc;  quc = t;
            t = qdp2; qdp2 = qdp1; qdp1 = qdc; qdc = t;
        }
    }
}

// ---------------------------------------------------------------------------
// Batch-mean over b (coalesced), still diag-major.
// ---------------------------------------------------------------------------
__global__ void reduce_kernel() {
    const int idx = blockIdx.x * blockDim.x + threadIdx.x;   // < ND*N
    float s = 0.0f;
    #pragma unroll 4
    for (int b = 0; b < NB; ++b) s += g_Ed[(size_t)b * ND * N + idx];
    g_Es[idx] = s * (1.0f / NB);
}

// ---------------------------------------------------------------------------
// Un-shear diag-major mean into the row-major output.
// ---------------------------------------------------------------------------
__global__ void gather_kernel(float* __restrict__ out) {
    const int idx = blockIdx.x * blockDim.x + threadIdx.x;   // < N*N
    const int i = idx >> 8, j = idx & (N - 1);
    out[idx] = g_Es[(i + j) * N + j];
}

// ---------------------------------------------------------------------------
extern "C" void kernel_launch(void* const* d_in, const int* in_sizes, int n_in,
                              void* d_out, int out_size) {
    const float* D = (const float*)d_in[0];
    float* out = (float*)d_out;

    shear_kernel<<<dim3(8, 8, NB), dim3(32, 8)>>>(D);
    dp_kernel<<<NB, 256>>>();
    reduce_kernel<<<ND, 256>>>();
    gather_kernel<<<(N * N) / 256, 256>>>(out);
}

// round 9
// speedup vs baseline: 2.7678x; 1.2431x over previous
#include <cuda_runtime.h>

#define NB   64
#define N    256
#define ND   511          // number of anti-diagonals (2N-1)
#define BIGV 1e10f

// Scratch (device globals; no allocations allowed).
// Diag-major layout: X[b][d][j] = cell (i=d-j, j) of batch b.
__device__ float g_Dd[NB * ND * N];   // sheared input costs
__device__ float g_Wl[NB * ND * N];   // softmin weight w_left  per cell
__device__ float g_Wd[NB * ND * N];   // softmin weight w_diag  per cell
__device__ float g_Wu[NB * ND * N];   // softmin weight w_up    per cell
__device__ float g_Ed[NB * ND * N];   // per-batch E
__device__ float g_Es[ND * N];        // batch-mean E (diag-major)

// ---------------------------------------------------------------------------
// Shear: row-major D -> diag-major g_Dd, coalesced both ways via smem tiles.
// ---------------------------------------------------------------------------
__global__ void shear_kernel(const float* __restrict__ D) {
    __shared__ float s[32][33];
    const int b  = blockIdx.z;
    const int i0 = blockIdx.y * 32;
    const int j0 = blockIdx.x * 32;
    const int tx = threadIdx.x, ty = threadIdx.y;

    const float* Db = D + (size_t)b * N * N;
    #pragma unroll
    for (int r = ty; r < 32; r += 8)
        s[r][tx] = Db[(i0 + r) * N + j0 + tx];
    __syncthreads();

    float* out = g_Dd + (size_t)b * ND * N;
    for (int dd = ty; dd < 63; dd += 8) {
        int r = dd - tx;
        if (r >= 0 && r < 32)
            out[(i0 + j0 + dd) * N + (j0 + tx)] = s[r][tx];
    }
}

// No-op spacers: shift dp_kernel to launch index 3, where ncu's -s 5 lands
// (abs skip 5 minus 2 harness-side launches, consistent across all rounds).
__global__ void noop_kernel() {}

// ---------------------------------------------------------------------------
// Fused forward + backward DP. One CTA per batch, thread j = column j.
// EXACT R4 structure; the only change is that smem carries
// z = __fdiv_rn(-R, 0.01f) (the same op every R4 consumer applied to R),
// so consumers skip their divides while every consumed value is bit-identical.
// ---------------------------------------------------------------------------
__global__ __launch_bounds__(256) void dp_kernel() {
    __shared__ float sb[10][N];

    const int b = blockIdx.x;
    const size_t base = (size_t)b * ND * N;
    const float* __restrict__ Dd = g_Dd + base;
    float* __restrict__ Wl = g_Wl + base;
    float* __restrict__ Wd = g_Wd + base;
    float* __restrict__ Wu = g_Wu + base;
    float* __restrict__ Ed = g_Ed + base;

    const int j = threadIdx.x;
    const bool jgt0 = (j > 0);
    const bool jlt  = (j < N - 1);
    const float ZBIG  = __fdiv_rn(-BIGV, 0.01f);
    const float ZZERO = __fdiv_rn(-0.0f, 0.01f);

    // ---------------- forward ----------------
    {
        float *zcur = sb[0], *zp1 = sb[1], *zp2 = sb[2];
        float th = Dd[j];                              // 1-deep prefetch (as R4)
        for (int d = 0; d < ND; ++d) {
            float th_next = 0.0f;
            if (d + 1 < ND) th_next = Dd[(size_t)(d + 1) * N + j];

            const int i = d - j;
            if ((unsigned)i < (unsigned)N) {
                const float zl = jgt0    ? zp1[j - 1] : ZBIG;       // z(i, j-1)
                const float zu = (i > 0) ? zp1[j]     : ZBIG;       // z(i-1, j)
                float zd;                                           // z(i-1, j-1)
                if (i > 0 && jgt0)       zd = zp2[j - 1];
                else                     zd = (i == 0 && j == 0) ? ZZERO : ZBIG;

                const float zmax = fmaxf(fmaxf(zl, zd), zu);
                const float el = expf(__fsub_rn(zl, zmax));
                const float ed = expf(__fsub_rn(zd, zmax));
                const float eu = expf(__fsub_rn(zu, zmax));
                const float ssum = __fadd_rn(__fadd_rn(el, ed), eu);
                const float lse  = __fadd_rn(logf(ssum), zmax);
                const float R    = __fadd_rn(th, __fmul_rn(-0.01f, lse));

                Wl[d * N + j] = expf(__fsub_rn(zl, lse));
                Wd[d * N + j] = expf(__fsub_rn(zd, lse));
                Wu[d * N + j] = expf(__fsub_rn(zu, lse));
                zcur[j] = __fdiv_rn(-R, 0.01f);
            }
            __syncthreads();
            th = th_next;
            float* t = zp2; zp2 = zp1; zp1 = zcur; zcur = t;
        }
    }

    // ---------------- backward (exact R4) ----------------
    {
        float *ecur = sb[0], *ep1 = sb[1], *ep2 = sb[2];
        float *qlc  = sb[3], *qlp = sb[4];                  // w_left  (cur, d+1)
        float *quc  = sb[5], *qup = sb[6];                  // w_up    (cur, d+1)
        float *qdc  = sb[7], *qdp1 = sb[8], *qdp2 = sb[9];  // w_diag  (cur, d+1, d+2)

        float wl = Wl[(size_t)(ND - 1) * N + j];            // 1-deep prefetch
        float wd = Wd[(size_t)(ND - 1) * N + j];
        float wu = Wu[(size_t)(ND - 1) * N + j];
        for (int d = ND - 1; d >= 0; --d) {
            float wl_n = 0.0f, wd_n = 0.0f, wu_n = 0.0f;
            if (d > 0) {
                wl_n = Wl[(size_t)(d - 1) * N + j];
                wd_n = Wd[(size_t)(d - 1) * N + j];
                wu_n = Wu[(size_t)(d - 1) * N + j];
            }

            const int i = d - j;
            if ((unsigned)i < (unsigned)N) {
                float e;
                if (i == N - 1 && j == N - 1) {
                    e = 1.0f;
                } else {
                    float t0 = 0.0f, t1 = 0.0f, t2 = 0.0f;
                    if (jlt)                       // from (i, j+1)  @ diag d+1
                        t0 = __fmul_rn(qlp[j + 1], ep1[j + 1]);
                    if (i < N - 1) {
                        if (jlt)                   // from (i+1,j+1) @ diag d+2
                            t1 = __fmul_rn(qdp2[j + 1], ep2[j + 1]);
                        t2 = __fmul_rn(qup[j], ep1[j]);   // from (i+1, j) @ d+1
                    }
                    e = __fadd_rn(__fadd_rn(t0, t1), t2);
                }
                Ed[(size_t)d * N + j] = e;
                ecur[j] = e;
                qlc[j] = wl;
                quc[j] = wu;
                qdc[j] = wd;
            }
            __syncthreads();
            wl = wl_n; wd = wd_n; wu = wu_n;
            float* t;
            t = ep2;  ep2  = ep1;  ep1 = ecur; ecur = t;
            t = qlp;  qlp  = qlc;  qlc = t;
            t = qup;  qup  = quc;  quc = t;
            t = qdp2; qdp2 = qdp1; qdp1 = qdc; qdc = t;
        }
    }
}

// ---------------------------------------------------------------------------
__global__ void reduce_kernel() {
    const int idx = blockIdx.x * blockDim.x + threadIdx.x;   // < ND*N
    float s = 0.0f;
    #pragma unroll 4
    for (int b = 0; b < NB; ++b) s += g_Ed[(size_t)b * ND * N + idx];
    g_Es[idx] = s * (1.0f / NB);
}

__global__ void gather_kernel(float* __restrict__ out) {
    const int idx = blockIdx.x * blockDim.x + threadIdx.x;   // < N*N
    const int i = idx >> 8, j = idx & (N - 1);
    out[idx] = g_Es[(i + j) * N + j];
}

// ---------------------------------------------------------------------------
extern "C" void kernel_launch(void* const* d_in, const int* in_sizes, int n_in,
                              void* d_out, int out_size) {
    const float* D = (const float*)d_in[0];
    float* out = (float*)d_out;

    shear_kernel<<<dim3(8, 8, NB), dim3(32, 8)>>>(D);   // launch 0
    noop_kernel<<<1, 32>>>();                           // launch 1 (spacer)
    noop_kernel<<<1, 32>>>();                           // launch 2 (spacer)
    dp_kernel<<<NB, 256>>>();                           // launch 3  <- ncu target
    reduce_kernel<<<ND, 256>>>();                       // launch 4
    gather_kernel<<<(N * N) / 256, 256>>>(out);         // launch 5
}